// round 14
// baseline (speedup 1.0000x reference)
#include <cuda_runtime.h>

constexpr int Lc = 2048;
constexpr int Ic = 32000;
constexpr int Dc = 256;

constexpr int KA_NB = 500;   // 64 DE rows per block (R5's proven k1 shape)
constexpr int KA_NT = 256;   // small CTAs -> many co-resident -> high MLP
constexpr int KO_NB = 250;   // 128 output cols per block
constexpr int KO_NT = 512;

// Scratch (device globals; allocation is forbidden).
// g_p starts zero (static init); the chain winner re-zeros it after reading,
// so the invariant "g_p == 0 at kernel entry" holds across graph replays.
__device__ float g_p[2][Dc];
__device__ float g_w[Dc];
__device__ unsigned g_count = 0;   // last-block ticket; winner self-resets

// ====== kA: dual GEMV p_k = x[L-2+k] @ DE  (+ fused chain in last block) ======
// R5-k1 access pattern: thread t owns output column t; 64 scalar DE loads,
// unroll 8; x rows staged in smem. atomicAdd accumulates across 500 blocks.
__global__ void __launch_bounds__(KA_NT) kA_posembed_chain(
    const float* __restrict__ x,   const float* __restrict__ DE,
    const float* __restrict__ PE,  const float* __restrict__ D1w,
    const float* __restrict__ Attw)
{
    __shared__ float sh[3072];     // GEMV: sx0/sx1 (128); chain: 3072
    __shared__ unsigned s_winner;
    const int t = threadIdx.x, b = blockIdx.x;

    // ---------------- GEMV over this block's 64 rows ----------------
    {
        float* sx0 = sh;
        float* sx1 = sh + 64;
        const int r0 = b * 64;
        if (t < 64)       sx0[t]      = x[(size_t)(Lc - 2) * Ic + r0 + t];
        else if (t < 128) sx1[t - 64] = x[(size_t)(Lc - 1) * Ic + r0 + t - 64];
        __syncthreads();

        float a0 = 0.f, a1 = 0.f;
        const float* de = DE + (size_t)r0 * Dc + t;
        #pragma unroll 8
        for (int r = 0; r < 64; ++r) {
            float v = de[(size_t)r * Dc];
            a0 = fmaf(sx0[r], v, a0);
            a1 = fmaf(sx1[r], v, a1);
        }
        atomicAdd(&g_p[0][t], a0);
        atomicAdd(&g_p[1][t], a1);
    }

    // Warm D1 + Att (+PE rows) into L2 for the chain tail
    {
        const int idx = b * KA_NT + t;
        if (idx < (2 * Dc * Dc) / 4) {          // blocks 0..127
            float4 v = __ldcg((const float4*)D1w  + idx);
            float4 u = __ldcg((const float4*)Attw + idx);
            asm volatile("" :: "f"(v.x + v.y + v.z + v.w + u.x + u.y + u.z + u.w));
        }
        if (b == 128 && t < 128) {
            float4 v = __ldcg((const float4*)(PE + (size_t)(Lc - 2) * Dc) + t);
            asm volatile("" :: "f"(v.x + v.y + v.z + v.w));
        }
    }

    // ---------------- last-block ticket ----------------
    __syncthreads();
    if (t == 0) {
        __threadfence();                        // publish this block's adds
        unsigned old = atomicAdd(&g_count, 1u);
        s_winner = (old == (unsigned)(KA_NB - 1));
        if (s_winner) {
            g_count = 0;                        // replay-safe self-reset
            __threadfence();                    // acquire: all g_p adds visible
        }
    }
    __syncthreads();
    if (!s_winner) return;

    // ------------- chain (winner block only; weights L2-hot) -------------
    const float inv1 = 1.0f / (float)(Lc - 1);
    const float inv2 = 1.0f / (float)Lc;
    float* sc0 = sh;            // 512
    float* sc1 = sh + 512;      // 512
    float* sp0 = sh + 1024;     // [4][256]
    float* sp1 = sh + 2048;     // [4][256]

    // read the fully-accumulated p rows, re-zero g_p for the next replay
    {
        float p0 = g_p[0][t] + PE[(size_t)(Lc - 2) * Dc + t];
        float p1 = g_p[1][t] + PE[(size_t)(Lc - 1) * Dc + t];
        g_p[0][t] = 0.f;
        g_p[1][t] = 0.f;
        sc0[t] = p0;  sc0[Dc + t] = (p0 + p1) * inv1;   // pool1 rows
        sc1[t] = p1;  sc1[Dc + t] = p1 * inv2;
        __syncthreads();
    }

    const int kk = t >> 6;      // 4-way k-split over the 512 concat dim
    const int cg = t & 63;      // 4 columns each (float4)
    float d0f = 0.f, d1f = 0.f;

    // dense1 = concat(p, pool1) @ D1
    {
        float d00=0,d01=0,d02=0,d03=0, d10=0,d11=0,d12=0,d13=0;
        #pragma unroll 8
        for (int k = kk; k < 2 * Dc; k += 4) {
            float4 v = *(const float4*)(D1w + (size_t)k * Dc + cg * 4);
            float c0 = sc0[k], c1 = sc1[k];
            d00 = fmaf(c0, v.x, d00); d01 = fmaf(c0, v.y, d01);
            d02 = fmaf(c0, v.z, d02); d03 = fmaf(c0, v.w, d03);
            d10 = fmaf(c1, v.x, d10); d11 = fmaf(c1, v.y, d11);
            d12 = fmaf(c1, v.z, d12); d13 = fmaf(c1, v.w, d13);
        }
        const int o = kk * 256 + cg * 4;
        sp0[o+0]=d00; sp0[o+1]=d01; sp0[o+2]=d02; sp0[o+3]=d03;
        sp1[o+0]=d10; sp1[o+1]=d11; sp1[o+2]=d12; sp1[o+3]=d13;
        __syncthreads();
        d0f = sp0[t] + sp0[256 + t] + sp0[512 + t] + sp0[768 + t];
        d1f = sp1[t] + sp1[256 + t] + sp1[512 + t] + sp1[768 + t];
        __syncthreads();
        sc0[t] = d0f;  sc0[Dc + t] = (d0f + d1f) * inv1;    // pool2 rows
        sc1[t] = d1f;  sc1[Dc + t] = d1f * inv2;
        __syncthreads();
    }

    // attention = concat(dense1, pool2) @ Att;  w = d0*a0 + d1*a1
    {
        float a00=0,a01=0,a02=0,a03=0, a10=0,a11=0,a12=0,a13=0;
        #pragma unroll 8
        for (int k = kk; k < 2 * Dc; k += 4) {
            float4 v = *(const float4*)(Attw + (size_t)k * Dc + cg * 4);
            float c0 = sc0[k], c1 = sc1[k];
            a00 = fmaf(c0, v.x, a00); a01 = fmaf(c0, v.y, a01);
            a02 = fmaf(c0, v.z, a02); a03 = fmaf(c0, v.w, a03);
            a10 = fmaf(c1, v.x, a10); a11 = fmaf(c1, v.y, a11);
            a12 = fmaf(c1, v.z, a12); a13 = fmaf(c1, v.w, a13);
        }
        const int o = kk * 256 + cg * 4;
        sp0[o+0]=a00; sp0[o+1]=a01; sp0[o+2]=a02; sp0[o+3]=a03;
        sp1[o+0]=a10; sp1[o+1]=a11; sp1[o+2]=a12; sp1[o+3]=a13;
        __syncthreads();
        float a0f = sp0[t] + sp0[256 + t] + sp0[512 + t] + sp0[768 + t];
        float a1f = sp1[t] + sp1[256 + t] + sp1[512 + t] + sp1[768 + t];
        g_w[t] = d0f * a0f + d1f * a1f;     // SA.T sum of the 2 surviving rows
    }
}

// ============ kOut: out[i] = sum_d w[d] * D2[d][i], one HBM pass ============
// 250 x 512. Thread (dg = t>>5 owns 16 d's, colg = t&31 owns 4 cols).
// Loads issued in explicit 8-deep batches to force MLP despite reg pressure.
__global__ void __launch_bounds__(KO_NT) kOut(
    const float* __restrict__ D2w, float* __restrict__ out)
{
    __shared__ float sw[Dc];
    __shared__ float red[16 * 128];
    const int t = threadIdx.x, b = blockIdx.x;
    const int colg = t & 31;
    const int dg   = t >> 5;     // 0..15

    if (t < Dc) sw[t] = g_w[t];
    __syncthreads();

    const float* base = D2w + (size_t)(dg * 16) * Ic + b * 128 + colg * 4;
    const float* swq  = sw + dg * 16;
    float4 acc = make_float4(0.f, 0.f, 0.f, 0.f);

    float4 vv[8];
    #pragma unroll
    for (int d = 0; d < 8; ++d) vv[d] = *(const float4*)(base + (size_t)d * Ic);
    #pragma unroll
    for (int d = 0; d < 8; ++d) {
        const float wv = swq[d];
        acc.x = fmaf(wv, vv[d].x, acc.x); acc.y = fmaf(wv, vv[d].y, acc.y);
        acc.z = fmaf(wv, vv[d].z, acc.z); acc.w = fmaf(wv, vv[d].w, acc.w);
    }
    #pragma unroll
    for (int d = 0; d < 8; ++d) vv[d] = *(const float4*)(base + (size_t)(8 + d) * Ic);
    #pragma unroll
    for (int d = 0; d < 8; ++d) {
        const float wv = swq[8 + d];
        acc.x = fmaf(wv, vv[d].x, acc.x); acc.y = fmaf(wv, vv[d].y, acc.y);
        acc.z = fmaf(wv, vv[d].z, acc.z); acc.w = fmaf(wv, vv[d].w, acc.w);
    }

    *(float4*)(red + dg * 128 + colg * 4) = acc;
    __syncthreads();
    if (t < 128) {
        float s = 0.f;
        #pragma unroll
        for (int j = 0; j < 16; ++j) s += red[j * 128 + t];
        out[b * 128 + t] = s;
    }
}

extern "C" void kernel_launch(void* const* d_in, const int* in_sizes, int n_in,
                              void* d_out, int out_size) {
    const float* x   = (const float*)d_in[0];  // [L, I]
    const float* DE  = (const float*)d_in[1];  // [I, D]
    const float* PE  = (const float*)d_in[2];  // [L, D]
    const float* D1w = (const float*)d_in[3];  // [2D, D]
    const float* D2w = (const float*)d_in[4];  // [D, I]
    const float* Att = (const float*)d_in[5];  // [2D, D]
    float* out = (float*)d_out;                // [1, I]
    (void)in_sizes; (void)n_in; (void)out_size;

    kA_posembed_chain<<<KA_NB, KA_NT>>>(x, DE, PE, D1w, Att);
    kOut<<<KO_NB, KO_NT>>>(D2w, out);
}

// round 15
// speedup vs baseline: 1.1291x; 1.1291x over previous
#include <cuda_runtime.h>

constexpr int Lc = 2048;
constexpr int Ic = 32000;
constexpr int Dc = 256;

constexpr int K1_NB = 1000;  // 32 DE rows per block -> ~6.8 CTAs/SM, high MLP
constexpr int K1_NT = 256;
constexpr int K2_NT = 512;   // single-block chain kernel
constexpr int K3_CC = 125;   // column chunks of 256
constexpr int K3_DS = 8;     // d-slices of 32
constexpr int K3_NB = K3_CC * K3_DS;   // 1000 blocks
constexpr int K3_NT = 256;

// Scratch (device globals; allocation is forbidden).
// g_p starts zero (static init); k2 re-zeros it after reading, so the
// invariant "g_p == 0 at k1 entry" holds across graph replays.
__device__ float g_p[2][Dc];
__device__ float g_w[Dc];

// ========== k1: dual GEMV p_k += x[L-2+k] @ DE (R5 pattern, 2x blocks) ==========
// Thread t owns output column t; block b owns DE rows [32b, 32b+32).
// Warp reads 128B contiguous per row; 8-deep unroll -> 8 lines in flight/warp;
// ~6.8 CTAs/SM -> ~54 warps/SM of independent loads.
__global__ void __launch_bounds__(K1_NT) k1_posembed(
    const float* __restrict__ x,   const float* __restrict__ DE,
    const float* __restrict__ D1w, const float* __restrict__ Attw)
{
    __shared__ float sx0[32], sx1[32];
    const int t = threadIdx.x, b = blockIdx.x;
    const int r0 = b * 32;

    if (t < 32)       sx0[t]      = x[(size_t)(Lc - 2) * Ic + r0 + t];
    else if (t < 64)  sx1[t - 32] = x[(size_t)(Lc - 1) * Ic + r0 + t - 32];
    __syncthreads();

    float a0 = 0.f, a1 = 0.f;
    const float* de = DE + (size_t)r0 * Dc + t;
    #pragma unroll 8
    for (int r = 0; r < 32; ++r) {
        float v = de[(size_t)r * Dc];
        a0 = fmaf(sx0[r], v, a0);
        a1 = fmaf(sx1[r], v, a1);
    }
    atomicAdd(&g_p[0][t], a0);
    atomicAdd(&g_p[1][t], a1);

    // Warm D1 + Att (1 MB) into L2 for k2 (blocks 0..127, one float4 pair each)
    const int idx = b * K1_NT + t;
    if (idx < (2 * Dc * Dc) / 4) {
        float4 v = __ldcg((const float4*)D1w  + idx);
        float4 u = __ldcg((const float4*)Attw + idx);
        asm volatile("" :: "f"(v.x + v.y + v.z + v.w + u.x + u.y + u.z + u.w));
    }
}

// ========== k2: the whole small chain in ONE kernel (1 block x 512) ==========
// p-read (+ re-zero g_p) -> dense1 -> attention -> w. Weights are L2-hot.
__global__ void __launch_bounds__(K2_NT) k2_chain(
    const float* __restrict__ PE, const float* __restrict__ D1w,
    const float* __restrict__ Attw)
{
    __shared__ float sc0[512], sc1[512];
    __shared__ float sp0[8 * 256], sp1[8 * 256];
    const int t = threadIdx.x;
    const float inv1 = 1.0f / (float)(Lc - 1);
    const float inv2 = 1.0f / (float)Lc;

    // p rows (+ PE bias); re-zero g_p for the next replay
    if (t < 256) {
        float p0 = g_p[0][t] + PE[(size_t)(Lc - 2) * Dc + t];
        float p1 = g_p[1][t] + PE[(size_t)(Lc - 1) * Dc + t];
        g_p[0][t] = 0.f;
        g_p[1][t] = 0.f;
        sc0[t] = p0;  sc0[Dc + t] = (p0 + p1) * inv1;   // pool1 rows
        sc1[t] = p1;  sc1[Dc + t] = p1 * inv2;
    }
    __syncthreads();

    const int kk = t >> 6;      // 8-way k-split over the 512 concat dim
    const int cg = t & 63;      // 4 columns each (float4)
    float d0f = 0.f, d1f = 0.f;

    // dense1 = concat(p, pool1) @ D1
    {
        float d00=0,d01=0,d02=0,d03=0, d10=0,d11=0,d12=0,d13=0;
        #pragma unroll 8
        for (int k = kk; k < 2 * Dc; k += 8) {
            float4 v = *(const float4*)(D1w + (size_t)k * Dc + cg * 4);
            float c0 = sc0[k], c1 = sc1[k];
            d00 = fmaf(c0, v.x, d00); d01 = fmaf(c0, v.y, d01);
            d02 = fmaf(c0, v.z, d02); d03 = fmaf(c0, v.w, d03);
            d10 = fmaf(c1, v.x, d10); d11 = fmaf(c1, v.y, d11);
            d12 = fmaf(c1, v.z, d12); d13 = fmaf(c1, v.w, d13);
        }
        const int o = kk * 256 + cg * 4;
        sp0[o+0]=d00; sp0[o+1]=d01; sp0[o+2]=d02; sp0[o+3]=d03;
        sp1[o+0]=d10; sp1[o+1]=d11; sp1[o+2]=d12; sp1[o+3]=d13;
        __syncthreads();
        if (t < 256) {
            #pragma unroll
            for (int j = 0; j < 8; ++j) { d0f += sp0[j*256+t]; d1f += sp1[j*256+t]; }
        }
        __syncthreads();
        if (t < 256) {
            sc0[t] = d0f;  sc0[Dc + t] = (d0f + d1f) * inv1;   // pool2 rows
            sc1[t] = d1f;  sc1[Dc + t] = d1f * inv2;
        }
        __syncthreads();
    }

    // attention = concat(dense1, pool2) @ Att;  w = d0*a0 + d1*a1
    {
        float a00=0,a01=0,a02=0,a03=0, a10=0,a11=0,a12=0,a13=0;
        #pragma unroll 8
        for (int k = kk; k < 2 * Dc; k += 8) {
            float4 v = *(const float4*)(Attw + (size_t)k * Dc + cg * 4);
            float c0 = sc0[k], c1 = sc1[k];
            a00 = fmaf(c0, v.x, a00); a01 = fmaf(c0, v.y, a01);
            a02 = fmaf(c0, v.z, a02); a03 = fmaf(c0, v.w, a03);
            a10 = fmaf(c1, v.x, a10); a11 = fmaf(c1, v.y, a11);
            a12 = fmaf(c1, v.z, a12); a13 = fmaf(c1, v.w, a13);
        }
        const int o = kk * 256 + cg * 4;
        sp0[o+0]=a00; sp0[o+1]=a01; sp0[o+2]=a02; sp0[o+3]=a03;
        sp1[o+0]=a10; sp1[o+1]=a11; sp1[o+2]=a12; sp1[o+3]=a13;
        __syncthreads();
        if (t < 256) {
            float a0f = 0.f, a1f = 0.f;
            #pragma unroll
            for (int j = 0; j < 8; ++j) { a0f += sp0[j*256+t]; a1f += sp1[j*256+t]; }
            g_w[t] = d0f * a0f + d1f * a1f;   // SA.T sum of the 2 surviving rows
        }
    }
}

// ========== k3: out[i] += sum_{d in slice} w[d] * D2[d][i]  (d-sliced) ==========
// 1000 blocks = 125 col-chunks x 8 d-slices; thread t = one output column.
// Warp reads 128B contiguous per d-row; 8-deep unroll; ~6.8 CTAs/SM.
// out must be zeroed before launch (cudaMemsetAsync in kernel_launch).
__global__ void __launch_bounds__(K3_NT) k3_out(
    const float* __restrict__ D2w, float* __restrict__ out)
{
    __shared__ float sw[32];
    const int t  = threadIdx.x, b = blockIdx.x;
    const int cc = b % K3_CC;        // column chunk
    const int ds = b / K3_CC;        // d-slice 0..7

    if (t < 32) sw[t] = g_w[ds * 32 + t];
    __syncthreads();

    const int i = cc * 256 + t;
    const float* base = D2w + (size_t)(ds * 32) * Ic + i;
    float acc = 0.f;
    #pragma unroll 8
    for (int d = 0; d < 32; ++d)
        acc = fmaf(sw[d], base[(size_t)d * Ic], acc);
    atomicAdd(&out[i], acc);
}

extern "C" void kernel_launch(void* const* d_in, const int* in_sizes, int n_in,
                              void* d_out, int out_size) {
    const float* x   = (const float*)d_in[0];  // [L, I]
    const float* DE  = (const float*)d_in[1];  // [I, D]
    const float* PE  = (const float*)d_in[2];  // [L, D]
    const float* D1w = (const float*)d_in[3];  // [2D, D]
    const float* D2w = (const float*)d_in[4];  // [D, I]
    const float* Att = (const float*)d_in[5];  // [2D, D]
    float* out = (float*)d_out;                // [1, I]
    (void)in_sizes; (void)n_in;

    cudaMemsetAsync(out, 0, (size_t)out_size * sizeof(float), 0);
    k1_posembed<<<K1_NB, K1_NT>>>(x, DE, D1w, Att);
    k2_chain<<<1, K2_NT>>>(PE, D1w, Att);
    k3_out<<<K3_NB, K3_NT>>>(D2w, out);
}

// round 17
// speedup vs baseline: 1.2195x; 1.0801x over previous
#include <cuda_runtime.h>

constexpr int Lc = 2048;
constexpr int Ic = 32000;
constexpr int Dc = 256;

// Phase 1: 1000 blocks, role by parity.
//   even b: DE-GEMV chunk (b>>1) of 500, 64 rows each  (R5's proven shape)
//   odd  b: D2 prefetch chunk (b>>1) of 500, 16384 floats each -> L2
constexpr int KP_NB = 1000;
constexpr int KP_NT = 256;
constexpr int K2_NT = 512;
constexpr int K3_CC = 125;            // column chunks of 256
constexpr int K3_DS = 8;              // d-slices of 32
constexpr int K3_NB = K3_CC * K3_DS;  // 1000 blocks
constexpr int K3_NT = 256;

// Scratch (device globals; allocation is forbidden).
// g_p starts zero (static init); k2 re-zeros it after reading, so the
// invariant "g_p == 0 at phase-1 entry" holds across graph replays.
__device__ float g_p[2][Dc];
__device__ float g_w[Dc];

// ============ kP: mixed-role phase 1 (DE-GEMV + D2->L2 prefetch) ============
__global__ void __launch_bounds__(KP_NT) kP_phase1(
    const float* __restrict__ x,   const float* __restrict__ DE,
    const float* __restrict__ D2w, const float* __restrict__ D1w,
    const float* __restrict__ Attw)
{
    const int t = threadIdx.x, b = blockIdx.x;

    if (b & 1) {
        // ---- D2 prefetch role: warm 65.6 KB into L2, then exit ----
        const int cb = b >> 1;                        // 0..499
        const float4* p = (const float4*)D2w + (size_t)cb * 4096 + t;
        float s = 0.f;
        #pragma unroll
        for (int j = 0; j < 16; ++j) {                // 16 independent 16B loads
            float4 v = __ldcg(p + j * 256);
            s += v.x + v.y + v.z + v.w;
        }
        // warm D1 + Att (1 MB) for k2 from the first 128 odd blocks
        const int idx = cb * KP_NT + t;
        if (idx < (2 * Dc * Dc) / 4) {
            float4 v = __ldcg((const float4*)D1w  + idx);
            float4 u = __ldcg((const float4*)Attw + idx);
            s += v.x + v.y + v.z + v.w + u.x + u.y + u.z + u.w;
        }
        asm volatile("" :: "f"(s));                   // keep the loads
        return;
    }

    // ---- DE-GEMV role (R5 k1 pattern): thread t = output column t ----
    __shared__ float sx0[64], sx1[64];
    const int cb = b >> 1;                            // 0..499
    const int r0 = cb * 64;
    if (t < 64)       sx0[t]      = x[(size_t)(Lc - 2) * Ic + r0 + t];
    else if (t < 128) sx1[t - 64] = x[(size_t)(Lc - 1) * Ic + r0 + t - 64];
    __syncthreads();

    float a0 = 0.f, a1 = 0.f;
    const float* de = DE + (size_t)r0 * Dc + t;
    #pragma unroll 8
    for (int r = 0; r < 64; ++r) {
        float v = de[(size_t)r * Dc];
        a0 = fmaf(sx0[r], v, a0);
        a1 = fmaf(sx1[r], v, a1);
    }
    atomicAdd(&g_p[0][t], a0);
    atomicAdd(&g_p[1][t], a1);
}

// ========== k2: the whole small chain in ONE kernel (1 block x 512) ==========
// p-read (+ re-zero g_p) -> dense1 -> attention -> w. Weights are L2-hot.
__global__ void __launch_bounds__(K2_NT) k2_chain(
    const float* __restrict__ PE, const float* __restrict__ D1w,
    const float* __restrict__ Attw)
{
    __shared__ float sc0[512], sc1[512];
    __shared__ float sp0[8 * 256], sp1[8 * 256];
    const int t = threadIdx.x;
    const float inv1 = 1.0f / (float)(Lc - 1);
    const float inv2 = 1.0f / (float)Lc;

    // p rows (+ PE bias); re-zero g_p for the next replay
    if (t < 256) {
        float p0 = g_p[0][t] + PE[(size_t)(Lc - 2) * Dc + t];
        float p1 = g_p[1][t] + PE[(size_t)(Lc - 1) * Dc + t];
        g_p[0][t] = 0.f;
        g_p[1][t] = 0.f;
        sc0[t] = p0;  sc0[Dc + t] = (p0 + p1) * inv1;   // pool1 rows
        sc1[t] = p1;  sc1[Dc + t] = p1 * inv2;
    }
    __syncthreads();

    const int kk = t >> 6;      // 8-way k-split over the 512 concat dim
    const int cg = t & 63;      // 4 columns each (float4)
    float d0f = 0.f, d1f = 0.f;

    // dense1 = concat(p, pool1) @ D1
    {
        float d00=0,d01=0,d02=0,d03=0, d10=0,d11=0,d12=0,d13=0;
        #pragma unroll 8
        for (int k = kk; k < 2 * Dc; k += 8) {
            float4 v = *(const float4*)(D1w + (size_t)k * Dc + cg * 4);
            float c0 = sc0[k], c1 = sc1[k];
            d00 = fmaf(c0, v.x, d00); d01 = fmaf(c0, v.y, d01);
            d02 = fmaf(c0, v.z, d02); d03 = fmaf(c0, v.w, d03);
            d10 = fmaf(c1, v.x, d10); d11 = fmaf(c1, v.y, d11);
            d12 = fmaf(c1, v.z, d12); d13 = fmaf(c1, v.w, d13);
        }
        const int o = kk * 256 + cg * 4;
        sp0[o+0]=d00; sp0[o+1]=d01; sp0[o+2]=d02; sp0[o+3]=d03;
        sp1[o+0]=d10; sp1[o+1]=d11; sp1[o+2]=d12; sp1[o+3]=d13;
        __syncthreads();
        if (t < 256) {
            #pragma unroll
            for (int j = 0; j < 8; ++j) { d0f += sp0[j*256+t]; d1f += sp1[j*256+t]; }
        }
        __syncthreads();
        if (t < 256) {
            sc0[t] = d0f;  sc0[Dc + t] = (d0f + d1f) * inv1;   // pool2 rows
            sc1[t] = d1f;  sc1[Dc + t] = d1f * inv2;
        }
        __syncthreads();
    }

    // attention = concat(dense1, pool2) @ Att;  w = d0*a0 + d1*a1
    {
        float a00=0,a01=0,a02=0,a03=0, a10=0,a11=0,a12=0,a13=0;
        #pragma unroll 8
        for (int k = kk; k < 2 * Dc; k += 8) {
            float4 v = *(const float4*)(Attw + (size_t)k * Dc + cg * 4);
            float c0 = sc0[k], c1 = sc1[k];
            a00 = fmaf(c0, v.x, a00); a01 = fmaf(c0, v.y, a01);
            a02 = fmaf(c0, v.z, a02); a03 = fmaf(c0, v.w, a03);
            a10 = fmaf(c1, v.x, a10); a11 = fmaf(c1, v.y, a11);
            a12 = fmaf(c1, v.z, a12); a13 = fmaf(c1, v.w, a13);
        }
        const int o = kk * 256 + cg * 4;
        sp0[o+0]=a00; sp0[o+1]=a01; sp0[o+2]=a02; sp0[o+3]=a03;
        sp1[o+0]=a10; sp1[o+1]=a11; sp1[o+2]=a12; sp1[o+3]=a13;
        __syncthreads();
        if (t < 256) {
            float a0f = 0.f, a1f = 0.f;
            #pragma unroll
            for (int j = 0; j < 8; ++j) { a0f += sp0[j*256+t]; a1f += sp1[j*256+t]; }
            g_w[t] = d0f * a0f + d1f * a1f;   // SA.T sum of the 2 surviving rows
        }
    }
}

// ========== k3: out[i] += sum_{d in slice} w[d] * D2[d][i]  (L2-served) ==========
// 1000 blocks = 125 col-chunks x 8 d-slices; thread t = one output column.
// D2 was warmed into L2 by kP; these are L2 hits, not the HBM pattern-cap.
// out is zeroed by the memset node before this launches.
__global__ void __launch_bounds__(K3_NT) k3_out(
    const float* __restrict__ D2w, float* __restrict__ out)
{
    __shared__ float sw[32];
    const int t  = threadIdx.x, b = blockIdx.x;
    const int cc = b % K3_CC;        // column chunk
    const int ds = b / K3_CC;        // d-slice 0..7

    if (t < 32) sw[t] = g_w[ds * 32 + t];
    __syncthreads();

    const int i = cc * 256 + t;
    const float* base = D2w + (size_t)(ds * 32) * Ic + i;
    float acc = 0.f;
    #pragma unroll 8
    for (int d = 0; d < 32; ++d)
        acc = fmaf(sw[d], base[(size_t)d * Ic], acc);
    atomicAdd(&out[i], acc);
}

extern "C" void kernel_launch(void* const* d_in, const int* in_sizes, int n_in,
                              void* d_out, int out_size) {
    const float* x   = (const float*)d_in[0];  // [L, I]
    const float* DE  = (const float*)d_in[1];  // [I, D]
    const float* PE  = (const float*)d_in[2];  // [L, D]
    const float* D1w = (const float*)d_in[3];  // [2D, D]
    const float* D2w = (const float*)d_in[4];  // [D, I]
    const float* Att = (const float*)d_in[5];  // [2D, D]
    float* out = (float*)d_out;                // [1, I]
    (void)in_sizes; (void)n_in;

    cudaMemsetAsync(out, 0, (size_t)out_size * sizeof(float), 0);
    kP_phase1<<<KP_NB, KP_NT>>>(x, DE, D2w, D1w, Att);
    k2_chain<<<1, K2_NT>>>(PE, D1w, Att);
    k3_out<<<K3_NB, K3_NT>>>(D2w, out);
}